// round 5
// baseline (speedup 1.0000x reference)
#include <cuda_runtime.h>
#include <math.h>

// Problem constants
#define BATCH 32
#define CH    512
#define HWSZ  4096          // 64*64
#define HID   64
#define FAN1  768

// Scratch (no allocs allowed in kernel_launch)
__device__ float g_xc[BATCH * CH];   // spatial means
__device__ float g_a [BATCH * CH];   // attention scalars

// ---------------------------------------------------------------------------
// Kernel 1: x_c[b,c] = mean over 4096 spatial elems. One block per (b,c) row.
// 256 threads, 4 float4 loads each (fully coalesced, 16 KB per block).
// ---------------------------------------------------------------------------
__global__ __launch_bounds__(256) void mean_pool_kernel(const float* __restrict__ x) {
    const int bc = blockIdx.x;
    const float4* __restrict__ xp =
        reinterpret_cast<const float4*>(x + (size_t)bc * HWSZ);
    const int tid = threadIdx.x;

    float s = 0.0f;
#pragma unroll
    for (int k = 0; k < 4; k++) {
        float4 v = xp[tid + k * 256];
        s += (v.x + v.y) + (v.z + v.w);
    }
#pragma unroll
    for (int o = 16; o; o >>= 1) s += __shfl_down_sync(0xffffffffu, s, o);

    __shared__ float ws[8];
    const int lane = tid & 31, w = tid >> 5;
    if (lane == 0) ws[w] = s;
    __syncthreads();
    if (tid == 0) {
        float t = 0.0f;
#pragma unroll
        for (int i = 0; i < 8; i++) t += ws[i];
        g_xc[bc] = t * (1.0f / HWSZ);
    }
}

// ---------------------------------------------------------------------------
// Kernel 2: per-batch attention scalars. One block per batch, 256 threads.
//   y[q]   = mean(xc[4q..4q+3])                               (q < 128)
//   A[h]   = dot(xc[0:512], W1[h,0:512]) + b1[h]
//   Bc[h]  = sum_q y[q] * (W1[h,512+q] + W1[h,640+q])
//   a[c]   = sigmoid( sum_h w2[h]*relu(A[h] + xc[c]*Bc[h]) + b2 )
// ---------------------------------------------------------------------------
__global__ __launch_bounds__(256) void attention_kernel(
    const float* __restrict__ w1,   // [64, 768] row-major
    const float* __restrict__ b1,   // [64]
    const float* __restrict__ w2,   // [1, 64]
    const float* __restrict__ b2)   // [1]
{
    __shared__ float xc[CH];
    __shared__ float yv[128];
    __shared__ float Aarr[HID];
    __shared__ float Barr[HID];
    __shared__ float w2s[HID];

    const int b   = blockIdx.x;
    const int tid = threadIdx.x;   // 256 threads

    xc[tid]       = g_xc[b * CH + tid];
    xc[tid + 256] = g_xc[b * CH + tid + 256];
    if (tid < HID) w2s[tid] = w2[tid];
    __syncthreads();

    if (tid < 128) {
        yv[tid] = 0.25f * (xc[4 * tid] + xc[4 * tid + 1] +
                           xc[4 * tid + 2] + xc[4 * tid + 3]);
    }
    __syncthreads();

    // 4 threads cooperate per h (coalesced W1 row reads)
    {
        const int h = tid >> 2;
        const int l = tid & 3;
        const float* __restrict__ wr = w1 + h * FAN1;
        float A = 0.0f, Bv = 0.0f;
#pragma unroll 8
        for (int j = l; j < CH; j += 4) A = fmaf(xc[j], wr[j], A);
#pragma unroll 8
        for (int q = l; q < 128; q += 4)
            Bv = fmaf(yv[q], wr[512 + q] + wr[640 + q], Bv);

        A  += __shfl_xor_sync(0xffffffffu, A, 1);
        A  += __shfl_xor_sync(0xffffffffu, A, 2);
        Bv += __shfl_xor_sync(0xffffffffu, Bv, 1);
        Bv += __shfl_xor_sync(0xffffffffu, Bv, 2);
        if (l == 0) { Aarr[h] = A + b1[h]; Barr[h] = Bv; }
    }
    __syncthreads();

    const float bias2 = b2[0];
#pragma unroll
    for (int cc = 0; cc < 2; cc++) {
        const int   c  = tid + cc * 256;
        const float xv = xc[c];
        float acc = bias2;
#pragma unroll
        for (int h = 0; h < HID; h++) {
            float sv = fmaf(xv, Barr[h], Aarr[h]);
            acc = fmaf(w2s[h], fmaxf(sv, 0.0f), acc);
        }
        g_a[b * CH + c] = 1.0f / (1.0f + expf(-acc));
    }
}

// ---------------------------------------------------------------------------
// Kernel 3: out = x * a[b,c]. One float4 per thread; 1024 float4 per (b,c)
// row so the 4 lanes of a vector share one 'a'.
// ---------------------------------------------------------------------------
__global__ __launch_bounds__(256) void scale_kernel(
    const float4* __restrict__ x, float4* __restrict__ out)
{
    const size_t i  = (size_t)blockIdx.x * 256 + threadIdx.x;
    const int    bc = (int)(i >> 10);       // 4096/4 = 1024 float4 per row
    const float  a  = __ldg(&g_a[bc]);
    float4 v = x[i];
    v.x *= a; v.y *= a; v.z *= a; v.w *= a;
    out[i] = v;
}

// ---------------------------------------------------------------------------
extern "C" void kernel_launch(void* const* d_in, const int* in_sizes, int n_in,
                              void* d_out, int out_size) {
    const float* x     = (const float*)d_in[0];  // [32,512,64,64]
    const float* fc1_w = (const float*)d_in[1];  // [64,768]
    const float* fc1_b = (const float*)d_in[2];  // [64]
    const float* fc2_w = (const float*)d_in[3];  // [1,64]
    const float* fc2_b = (const float*)d_in[4];  // [1]
    float* out = (float*)d_out;

    mean_pool_kernel<<<BATCH * CH, 256>>>(x);
    attention_kernel<<<BATCH, 256>>>(fc1_w, fc1_b, fc2_w, fc2_b);

    const int n4 = BATCH * CH * HWSZ / 4;        // 16,777,216
    scale_kernel<<<n4 / 256, 256>>>(
        reinterpret_cast<const float4*>(x), reinterpret_cast<float4*>(out));
}

// round 6
// speedup vs baseline: 1.0718x; 1.0718x over previous
#include <cuda_runtime.h>
#include <math.h>

// Problem constants
#define BATCH 32
#define CH    512
#define HWSZ  4096          // 64*64
#define HID   64
#define FAN1  768

// Scratch (no allocs allowed in kernel_launch)
__device__ float g_xc[BATCH * CH];   // spatial means
__device__ float g_a [BATCH * CH];   // attention scalars

// ---------------------------------------------------------------------------
// Kernel 1: x_c[b,c] = mean over 4096 spatial elems. One block per (b,c) row.
// 256 threads, 4 float4 loads each (fully coalesced, 16 KB per block).
// Reads are LEFT IN L2 on purpose: the scale kernel consumes the tail of x
// from L2 by walking in reverse order.
// ---------------------------------------------------------------------------
__global__ __launch_bounds__(256) void mean_pool_kernel(const float* __restrict__ x) {
    const int bc = blockIdx.x;
    const float4* __restrict__ xp =
        reinterpret_cast<const float4*>(x + (size_t)bc * HWSZ);
    const int tid = threadIdx.x;

    // Batch all 4 loads up front for MLP
    float4 v0 = xp[tid];
    float4 v1 = xp[tid + 256];
    float4 v2 = xp[tid + 512];
    float4 v3 = xp[tid + 768];

    float s = ((v0.x + v0.y) + (v0.z + v0.w))
            + ((v1.x + v1.y) + (v1.z + v1.w))
            + ((v2.x + v2.y) + (v2.z + v2.w))
            + ((v3.x + v3.y) + (v3.z + v3.w));

#pragma unroll
    for (int o = 16; o; o >>= 1) s += __shfl_down_sync(0xffffffffu, s, o);

    __shared__ float ws[8];
    const int lane = tid & 31, w = tid >> 5;
    if (lane == 0) ws[w] = s;
    __syncthreads();
    if (tid == 0) {
        float t = 0.0f;
#pragma unroll
        for (int i = 0; i < 8; i++) t += ws[i];
        g_xc[bc] = t * (1.0f / HWSZ);
    }
}

// ---------------------------------------------------------------------------
// Kernel 2: per-batch attention scalars. One block per batch, 256 threads.
//   y[q]   = mean(xc[4q..4q+3])                               (q < 128)
//   A[h]   = dot(xc[0:512], W1[h,0:512]) + b1[h]
//   Bc[h]  = sum_q y[q] * (W1[h,512+q] + W1[h,640+q])
//   a[c]   = sigmoid( sum_h w2[h]*relu(A[h] + xc[c]*Bc[h]) + b2 )
// ---------------------------------------------------------------------------
__global__ __launch_bounds__(256) void attention_kernel(
    const float* __restrict__ w1,   // [64, 768] row-major
    const float* __restrict__ b1,   // [64]
    const float* __restrict__ w2,   // [1, 64]
    const float* __restrict__ b2)   // [1]
{
    __shared__ float xc[CH];
    __shared__ float yv[128];
    __shared__ float Aarr[HID];
    __shared__ float Barr[HID];
    __shared__ float w2s[HID];

    const int b   = blockIdx.x;
    const int tid = threadIdx.x;   // 256 threads

    xc[tid]       = g_xc[b * CH + tid];
    xc[tid + 256] = g_xc[b * CH + tid + 256];
    if (tid < HID) w2s[tid] = w2[tid];
    __syncthreads();

    if (tid < 128) {
        yv[tid] = 0.25f * (xc[4 * tid] + xc[4 * tid + 1] +
                           xc[4 * tid + 2] + xc[4 * tid + 3]);
    }
    __syncthreads();

    // 4 threads cooperate per h (coalesced W1 row reads)
    {
        const int h = tid >> 2;
        const int l = tid & 3;
        const float* __restrict__ wr = w1 + h * FAN1;
        float A = 0.0f, Bv = 0.0f;
#pragma unroll 8
        for (int j = l; j < CH; j += 4) A = fmaf(xc[j], wr[j], A);
#pragma unroll 8
        for (int q = l; q < 128; q += 4)
            Bv = fmaf(yv[q], wr[512 + q] + wr[640 + q], Bv);

        A  += __shfl_xor_sync(0xffffffffu, A, 1);
        A  += __shfl_xor_sync(0xffffffffu, A, 2);
        Bv += __shfl_xor_sync(0xffffffffu, Bv, 1);
        Bv += __shfl_xor_sync(0xffffffffu, Bv, 2);
        if (l == 0) { Aarr[h] = A + b1[h]; Barr[h] = Bv; }
    }
    __syncthreads();

    const float bias2 = b2[0];
#pragma unroll
    for (int cc = 0; cc < 2; cc++) {
        const int   c  = tid + cc * 256;
        const float xv = xc[c];
        float acc = bias2;
#pragma unroll
        for (int h = 0; h < HID; h++) {
            float sv = fmaf(xv, Barr[h], Aarr[h]);
            acc = fmaf(w2s[h], fmaxf(sv, 0.0f), acc);
        }
        g_a[b * CH + c] = 1.0f / (1.0f + expf(-acc));
    }
}

// ---------------------------------------------------------------------------
// Kernel 3: out = x * a[b,c].
//  - REVERSE block order: mean_pool left the tail of x in L2; consume it
//    first (up to ~126 MB of the 268 MB re-read comes from L2, not HBM).
//  - 2 independent float4 per thread, loads batched before stores (MLP).
//  - __ldcs on x (no further reuse), __stcs on out (evict-first: don't let
//    store-allocate evict the x tail we haven't consumed yet).
// ---------------------------------------------------------------------------
__global__ __launch_bounds__(256) void scale_kernel(
    const float4* __restrict__ x, float4* __restrict__ out)
{
    const int    rb   = (int)gridDim.x - 1 - (int)blockIdx.x;
    const size_t base = (size_t)rb * 512 + threadIdx.x;
    const size_t i0 = base, i1 = base + 256;

    float4 v0 = __ldcs(&x[i0]);
    float4 v1 = __ldcs(&x[i1]);
    const float a0 = __ldg(&g_a[(int)(i0 >> 10)]);   // 1024 float4 per (b,c) row
    const float a1 = __ldg(&g_a[(int)(i1 >> 10)]);

    v0.x *= a0; v0.y *= a0; v0.z *= a0; v0.w *= a0;
    v1.x *= a1; v1.y *= a1; v1.z *= a1; v1.w *= a1;

    __stcs(&out[i0], v0);
    __stcs(&out[i1], v1);
}

// ---------------------------------------------------------------------------
extern "C" void kernel_launch(void* const* d_in, const int* in_sizes, int n_in,
                              void* d_out, int out_size) {
    const float* x     = (const float*)d_in[0];  // [32,512,64,64]
    const float* fc1_w = (const float*)d_in[1];  // [64,768]
    const float* fc1_b = (const float*)d_in[2];  // [64]
    const float* fc2_w = (const float*)d_in[3];  // [1,64]
    const float* fc2_b = (const float*)d_in[4];  // [1]
    float* out = (float*)d_out;

    mean_pool_kernel<<<BATCH * CH, 256>>>(x);
    attention_kernel<<<BATCH, 256>>>(fc1_w, fc1_b, fc2_w, fc2_b);

    const int n4 = BATCH * CH * HWSZ / 4;        // 16,777,216 float4
    scale_kernel<<<n4 / 512, 256>>>(             // 32768 blocks, 2 float4/thread
        reinterpret_cast<const float4*>(x), reinterpret_cast<float4*>(out));
}